// round 10
// baseline (speedup 1.0000x reference)
#include <cuda_runtime.h>
#include <math.h>
#include <cstdint>

#define N_PTS 16384
#define DIM 256
#define HEADS 8
#define HD 32
#define KNN 20
#define MLP_HID 1024
#define SCALE 0.17677669529663687f  // 32^-0.5
#define FULLMASK 0xffffffffu

// spatial grid for kNN
#define NB 16
#define NBINS (NB * NB * NB)
#define XMIN (-4.25f)
#define CELL 0.53125f
#define INVCELL (1.0f / CELL)
#define DINF 3.0e38f
#define IINF 0x7fffffff

// ---------------- scratch (device globals; no allocation allowed) ----------
__device__ float g_h[N_PTS * DIM];       // LN1 out, later reused for LN2 out
__device__ float g_q[N_PTS * DIM];
__device__ float g_k[N_PTS * DIM];
__device__ float g_v[N_PTS * DIM];
__device__ float g_attn[N_PTS * DIM];
__device__ float g_x1[N_PTS * DIM];      // residual-1 result
__device__ float g_hid[N_PTS * MLP_HID];
__device__ int   g_knn[N_PTS * KNN];
__device__ float4 g_pos4[N_PTS];         // original-order positions
__device__ int   g_bincnt[NBINS];
__device__ int   g_binstart[NBINS + 1];
__device__ int   g_cursor[NBINS];
__device__ float4 g_spos[N_PTS];         // bin-sorted positions
__device__ int   g_sidx[N_PTS];          // bin-sorted original indices

// ---------------- mma helpers ----------------------------------------------
__device__ __forceinline__ void mma_tf32(float* c, const uint32_t* a, const uint32_t* b) {
    asm volatile(
        "mma.sync.aligned.m16n8k8.row.col.f32.tf32.tf32.f32 "
        "{%0,%1,%2,%3}, {%4,%5,%6,%7}, {%8,%9}, {%0,%1,%2,%3};"
        : "+f"(c[0]), "+f"(c[1]), "+f"(c[2]), "+f"(c[3])
        : "r"(a[0]), "r"(a[1]), "r"(a[2]), "r"(a[3]), "r"(b[0]), "r"(b[1]));
}

__device__ __forceinline__ uint32_t s2u(const void* smem_ptr) {
    uint32_t addr;
    asm("{ .reg .u64 tmp; cvta.to.shared.u64 tmp, %1; cvt.u32.u64 %0, tmp; }"
        : "=r"(addr) : "l"(smem_ptr));
    return addr;
}

__device__ __forceinline__ void cp_async16(uint32_t smem_addr, const void* gptr) {
    asm volatile("cp.async.cg.shared.global [%0], [%1], 16;"
                 :: "r"(smem_addr), "l"(gptr));
}
__device__ __forceinline__ void cp_commit() {
    asm volatile("cp.async.commit_group;");
}
template <int NN>
__device__ __forceinline__ void cp_wait() {
    asm volatile("cp.async.wait_group %0;" :: "n"(NN));
}

// ==================== tf32 mma.sync GEMM (2-stage, 3 CTAs/SM) ==============
// C[M,Nn] = act(A[M,Kd] * B[Nn,Kd]^T + bias) [+ R]
// CTA tile 128x128, 8 warps (4m x 2n), warp tile 32x64, K chunk 32.
// 2-stage cp.async pipeline, one barrier per chunk:
//   wait(oldest) -> barrier -> issue(ch+1) -> compute(ch)
// issue(ch+1) overwrites buf (ch+1)&1, last read by compute(ch-1) which the
// barrier just fenced. __launch_bounds__(256,3) caps regs at 85 so
// 3 CTAs/SM fit both RF and the 216KB smem budget.
#define SK 36
#define BUFELEMS (128 * SK)
#define NSTAGE 2
#define SMEM_BYTES (2 * NSTAGE * BUFELEMS * 4)   // 72 KB

template <int ACT, int RES>
__global__ __launch_bounds__(256, 3) void tc_gemm(const float* __restrict__ A,
                                                  const float* __restrict__ B0,
                                                  const float* __restrict__ B1,
                                                  const float* __restrict__ B2,
                                                  const float* __restrict__ bias0,
                                                  const float* __restrict__ bias1,
                                                  const float* __restrict__ bias2,
                                                  float* __restrict__ C0,
                                                  float* __restrict__ C1,
                                                  float* __restrict__ C2,
                                                  const float* __restrict__ R,
                                                  int M, int Nn, int Kd) {
    extern __shared__ float smem[];
    float* AsBase = smem;                       // [NSTAGE][BUFELEMS]
    float* BsBase = smem + NSTAGE * BUFELEMS;   // [NSTAGE][BUFELEMS]

    const float* B    = (blockIdx.z == 0) ? B0    : (blockIdx.z == 1) ? B1    : B2;
    const float* bias = (blockIdx.z == 0) ? bias0 : (blockIdx.z == 1) ? bias1 : bias2;
    float*       C    = (blockIdx.z == 0) ? C0    : (blockIdx.z == 1) ? C1    : C2;

    const int tid = threadIdx.x;
    const int wid = tid >> 5;
    const int lane = tid & 31;
    const int g = lane >> 2;
    const int t = lane & 3;
    const int m0 = blockIdx.y * 128;
    const int n0 = blockIdx.x * 128;
    const int wm = (wid >> 1) * 32;
    const int wn = (wid & 1) * 64;

    float acc[2][8][4];
#pragma unroll
    for (int mt = 0; mt < 2; mt++)
#pragma unroll
        for (int nt = 0; nt < 8; nt++)
#pragma unroll
            for (int j = 0; j < 4; j++) acc[mt][nt][j] = 0.0f;

    const int srow = tid >> 1;
    const int skq  = (tid & 1) * 16;

    const float* agbase = A + (size_t)(m0 + srow) * Kd + skq;
    const float* bgbase = B + (size_t)(n0 + srow) * Kd + skq;
    const int nch = Kd >> 5;

    auto issue = [&](int ch) {
        const int buf = ch & 1;
        const float* ag = agbase + ch * 32;
        const float* bg = bgbase + ch * 32;
        uint32_t as = s2u(AsBase + buf * BUFELEMS + srow * SK + skq);
        uint32_t bs = s2u(BsBase + buf * BUFELEMS + srow * SK + skq);
#pragma unroll
        for (int j = 0; j < 4; j++) {
            cp_async16(as + j * 16, ag + j * 4);
            cp_async16(bs + j * 16, bg + j * 4);
        }
        cp_commit();
    };

    issue(0);
    for (int ch = 0; ch < nch; ++ch) {
        cp_wait<0>();
        __syncthreads();
        if (ch + 1 < nch) issue(ch + 1);

        const float* As = AsBase + (ch & 1) * BUFELEMS;
        const float* Bs = BsBase + (ch & 1) * BUFELEMS;
#pragma unroll
        for (int ks = 0; ks < 4; ks++) {
            const int kk = ks * 8;
            uint32_t a[2][4];
#pragma unroll
            for (int mt = 0; mt < 2; mt++) {
                const float* ap = As + (wm + mt * 16 + g) * SK + kk + t;
                a[mt][0] = __float_as_uint(ap[0]);
                a[mt][1] = __float_as_uint(ap[8 * SK]);
                a[mt][2] = __float_as_uint(ap[4]);
                a[mt][3] = __float_as_uint(ap[8 * SK + 4]);
            }
            uint32_t b[8][2];
#pragma unroll
            for (int nt = 0; nt < 8; nt++) {
                const float* bp = Bs + (wn + nt * 8 + g) * SK + kk + t;
                b[nt][0] = __float_as_uint(bp[0]);
                b[nt][1] = __float_as_uint(bp[4]);
            }
#pragma unroll
            for (int mt = 0; mt < 2; mt++)
#pragma unroll
                for (int nt = 0; nt < 8; nt++)
                    mma_tf32(acc[mt][nt], a[mt], b[nt]);
        }
    }

#pragma unroll
    for (int mt = 0; mt < 2; mt++) {
#pragma unroll
        for (int half = 0; half < 2; half++) {
            const int m = m0 + wm + mt * 16 + g + half * 8;
            float* crow = C + (size_t)m * Nn + n0 + wn;
            const float* rrow = R + (size_t)m * Nn + n0 + wn;
#pragma unroll
            for (int nt = 0; nt < 8; nt++) {
                const int nc = nt * 8 + 2 * t;
                float2 c;
                c.x = acc[mt][nt][half * 2 + 0] + bias[n0 + wn + nc + 0];
                c.y = acc[mt][nt][half * 2 + 1] + bias[n0 + wn + nc + 1];
                if (ACT == 1) {
                    c.x = 0.5f * c.x * (1.0f + erff(c.x * 0.70710678118654752f));
                    c.y = 0.5f * c.y * (1.0f + erff(c.y * 0.70710678118654752f));
                }
                if (RES) {
                    c.x += rrow[nc + 0];
                    c.y += rrow[nc + 1];
                }
                *(float2*)(crow + nc) = c;
            }
        }
    }
}

// ==================== grid-binned exact kNN ====================
__device__ __forceinline__ int bin_of(float x) {
    int b = (int)floorf((x - XMIN) * INVCELL);
    return min(NB - 1, max(0, b));
}

__global__ __launch_bounds__(256) void zero_bins_kernel() {
    const int i = blockIdx.x * blockDim.x + threadIdx.x;
    if (i < NBINS) g_bincnt[i] = 0;
}

__global__ __launch_bounds__(256) void pack_count_kernel(const float* __restrict__ pos) {
    const int i = blockIdx.x * blockDim.x + threadIdx.x;
    float4 p;
    p.x = pos[i * 3 + 0];
    p.y = pos[i * 3 + 1];
    p.z = pos[i * 3 + 2];
    p.w = 0.0f;
    g_pos4[i] = p;
    const int b = (bin_of(p.z) * NB + bin_of(p.y)) * NB + bin_of(p.x);
    atomicAdd(&g_bincnt[b], 1);
}

__global__ __launch_bounds__(1024) void scan_kernel() {
    __shared__ int ssum[1024];
    const int t = threadIdx.x;
    int c0 = g_bincnt[4 * t + 0];
    int c1 = g_bincnt[4 * t + 1];
    int c2 = g_bincnt[4 * t + 2];
    int c3 = g_bincnt[4 * t + 3];
    const int s = c0 + c1 + c2 + c3;
    ssum[t] = s;
    __syncthreads();
    for (int off = 1; off < 1024; off <<= 1) {
        int v = (t >= off) ? ssum[t - off] : 0;
        __syncthreads();
        ssum[t] += v;
        __syncthreads();
    }
    int excl = ssum[t] - s;
    g_binstart[4 * t + 0] = excl;
    g_cursor[4 * t + 0]   = excl;
    excl += c0;
    g_binstart[4 * t + 1] = excl;
    g_cursor[4 * t + 1]   = excl;
    excl += c1;
    g_binstart[4 * t + 2] = excl;
    g_cursor[4 * t + 2]   = excl;
    excl += c2;
    g_binstart[4 * t + 3] = excl;
    g_cursor[4 * t + 3]   = excl;
    if (t == 1023) g_binstart[NBINS] = N_PTS;
}

__global__ __launch_bounds__(256) void scatter_kernel() {
    const int i = blockIdx.x * blockDim.x + threadIdx.x;
    const float4 p = g_pos4[i];
    const int b = (bin_of(p.z) * NB + bin_of(p.y)) * NB + bin_of(p.x);
    const int pos = atomicAdd(&g_cursor[b], 1);
    g_spos[pos] = p;
    g_sidx[pos] = i;
}

// warp-per-query shell-expanding exact kNN (lexicographic (d, idx) top-21).
__global__ __launch_bounds__(256) void knn_bins_kernel() {
    const int lane = threadIdx.x & 31;
    const int warp = threadIdx.x >> 5;
    const int qi = blockIdx.x * 8 + warp;

    const float4 qp = g_pos4[qi];
    const float qx = qp.x, qy = qp.y, qz = qp.z;
    const int qbx = bin_of(qx), qby = bin_of(qy), qbz = bin_of(qz);

    float list_d = DINF;
    int   list_i = IINF;
    float tau = DINF;
    int   tau_i = IINF;

    for (int r = 0; r < NB; ++r) {
        if (r >= 2) {
            const float sm = (float)(r - 1) * CELL;
            if (sm * sm > tau * 1.001f) break;
        }
        for (int dz = -r; dz <= r; ++dz) {
            const int zz = qbz + dz;
            if (zz < 0 || zz >= NB) continue;
            for (int dy = -r; dy <= r; ++dy) {
                const int yy = qby + dy;
                if (yy < 0 || yy >= NB) continue;
                const bool face = (dz == r || dz == -r || dy == r || dy == -r);
                const int step = (face || r == 0) ? 1 : 2 * r;
                for (int dx = -r; dx <= r; dx += step) {
                    const int xx = qbx + dx;
                    if (xx < 0 || xx >= NB) continue;
                    const int bin = (zz * NB + yy) * NB + xx;
                    const int s0 = g_binstart[bin];
                    const int s1 = g_binstart[bin + 1];
                    if (s0 == s1) continue;

                    const float lox = (xx == 0)      ? -1e30f : XMIN + xx * CELL;
                    const float hix = (xx == NB - 1) ?  1e30f : XMIN + (xx + 1) * CELL;
                    const float loy = (yy == 0)      ? -1e30f : XMIN + yy * CELL;
                    const float hiy = (yy == NB - 1) ?  1e30f : XMIN + (yy + 1) * CELL;
                    const float loz = (zz == 0)      ? -1e30f : XMIN + zz * CELL;
                    const float hiz = (zz == NB - 1) ?  1e30f : XMIN + (zz + 1) * CELL;
                    const float ddx = fmaxf(0.0f, fmaxf(lox - qx, qx - hix));
                    const float ddy = fmaxf(0.0f, fmaxf(loy - qy, qy - hiy));
                    const float ddz = fmaxf(0.0f, fmaxf(loz - qz, qz - hiz));
                    const float mind2 = ddx * ddx + ddy * ddy + ddz * ddz;
                    if (mind2 > tau * 1.001f) continue;

                    for (int off = s0; off < s1; off += 32) {
                        const int j = off + lane;
                        float d = DINF;
                        int ci = IINF;
                        if (j < s1) {
                            const float4 c = g_spos[j];
                            const float ex = qx - c.x;
                            const float ey = qy - c.y;
                            const float ez = qz - c.z;
                            d = ex * ex + ey * ey + ez * ez;
                            ci = g_sidx[j];
                        }
                        const bool cand = (d < tau) || (d == tau && ci < tau_i);
                        unsigned m = __ballot_sync(FULLMASK, cand);
                        while (m) {
                            const int src = __ffs(m) - 1;
                            m &= m - 1;
                            const float d_new = __shfl_sync(FULLMASK, d, src);
                            const int   i_new = __shfl_sync(FULLMASK, ci, src);
                            if (d_new < tau || (d_new == tau && i_new < tau_i)) {
                                const unsigned less = __ballot_sync(FULLMASK,
                                    (list_d < d_new) || (list_d == d_new && list_i < i_new));
                                const int pos = __popc(less);
                                const float d_up = __shfl_up_sync(FULLMASK, list_d, 1);
                                const int   i_up = __shfl_up_sync(FULLMASK, list_i, 1);
                                if (lane > pos)       { list_d = d_up;  list_i = i_up;  }
                                else if (lane == pos) { list_d = d_new; list_i = i_new; }
                                if (lane > 20)        { list_d = DINF;  list_i = IINF;  }
                                tau   = __shfl_sync(FULLMASK, list_d, 20);
                                tau_i = __shfl_sync(FULLMASK, list_i, 20);
                            }
                        }
                    }
                }
            }
        }
    }
    if (lane >= 1 && lane <= 20)
        g_knn[qi * KNN + (lane - 1)] = list_i;
}

// ---------------- LayerNorm: one warp per row ------------------------------
__global__ __launch_bounds__(256) void ln_kernel(const float* __restrict__ x,
                                                 const float* __restrict__ w,
                                                 const float* __restrict__ b,
                                                 float* __restrict__ out) {
    const int warp = threadIdx.x >> 5;
    const int lane = threadIdx.x & 31;
    const int n = blockIdx.x * 8 + warp;
    const float4* xr = (const float4*)(x + (size_t)n * DIM + lane * 8);
    float4 a0 = xr[0], a1 = xr[1];
    float s1 = a0.x + a0.y + a0.z + a0.w + a1.x + a1.y + a1.z + a1.w;
    float s2 = a0.x * a0.x + a0.y * a0.y + a0.z * a0.z + a0.w * a0.w +
               a1.x * a1.x + a1.y * a1.y + a1.z * a1.z + a1.w * a1.w;
#pragma unroll
    for (int off = 16; off > 0; off >>= 1) {
        s1 += __shfl_xor_sync(0xffffffffu, s1, off);
        s2 += __shfl_xor_sync(0xffffffffu, s2, off);
    }
    float m = s1 * (1.0f / DIM);
    float var = s2 * (1.0f / DIM) - m * m;
    float r = rsqrtf(var + 1e-5f);
    const float4* wr = (const float4*)(w + lane * 8);
    const float4* br = (const float4*)(b + lane * 8);
    float4 w0 = wr[0], w1 = wr[1], b0 = br[0], b1 = br[1];
    float4 o0, o1;
    o0.x = (a0.x - m) * r * w0.x + b0.x;
    o0.y = (a0.y - m) * r * w0.y + b0.y;
    o0.z = (a0.z - m) * r * w0.z + b0.z;
    o0.w = (a0.w - m) * r * w0.w + b0.w;
    o1.x = (a1.x - m) * r * w1.x + b1.x;
    o1.y = (a1.y - m) * r * w1.y + b1.y;
    o1.z = (a1.z - m) * r * w1.z + b1.z;
    o1.w = (a1.w - m) * r * w1.w + b1.w;
    float4* orow = (float4*)(out + (size_t)n * DIM + lane * 8);
    orow[0] = o0; orow[1] = o1;
}

// ---------------- local attention: one warp per point ----------------------
__global__ __launch_bounds__(256) void attn_kernel(const float* __restrict__ q,
                                                   const float* __restrict__ k,
                                                   const float* __restrict__ v,
                                                   const int* __restrict__ knn,
                                                   float* __restrict__ out) {
    const int warp = threadIdx.x >> 5;
    const int lane = threadIdx.x & 31;
    const int n = blockIdx.x * 8 + warp;
    const float4* qr = (const float4*)(q + (size_t)n * DIM + lane * 8);
    float4 q0 = qr[0], q1 = qr[1];

    int idx[KNN];
#pragma unroll
    for (int j = 0; j < KNN; j++) idx[j] = knn[n * KNN + j];

    float w[KNN];
#pragma unroll
    for (int j = 0; j < KNN; j++) {
        const float4* kr = (const float4*)(k + (size_t)idx[j] * DIM + lane * 8);
        float4 k0 = kr[0], k1 = kr[1];
        float s = q0.x * k0.x + q0.y * k0.y + q0.z * k0.z + q0.w * k0.w +
                  q1.x * k1.x + q1.y * k1.y + q1.z * k1.z + q1.w * k1.w;
        s += __shfl_xor_sync(0xffffffffu, s, 1);
        s += __shfl_xor_sync(0xffffffffu, s, 2);
        w[j] = s * SCALE;
    }
    float mx = -3.0e38f;
#pragma unroll
    for (int j = 0; j < KNN; j++) mx = fmaxf(mx, w[j]);
    float sum = 0.0f;
#pragma unroll
    for (int j = 0; j < KNN; j++) { w[j] = expf(w[j] - mx); sum += w[j]; }
    const float inv = 1.0f / sum;

    float4 o0 = {0, 0, 0, 0}, o1 = {0, 0, 0, 0};
#pragma unroll
    for (int j = 0; j < KNN; j++) {
        const float wj = w[j] * inv;
        const float4* vr = (const float4*)(v + (size_t)idx[j] * DIM + lane * 8);
        float4 v0 = vr[0], v1 = vr[1];
        o0.x += wj * v0.x; o0.y += wj * v0.y; o0.z += wj * v0.z; o0.w += wj * v0.w;
        o1.x += wj * v1.x; o1.y += wj * v1.y; o1.z += wj * v1.z; o1.w += wj * v1.w;
    }
    float4* orow = (float4*)(out + (size_t)n * DIM + lane * 8);
    orow[0] = o0; orow[1] = o1;
}

// ---------------- launch ---------------------------------------------------
extern "C" void kernel_launch(void* const* d_in, const int* in_sizes, int n_in,
                              void* d_out, int out_size) {
    const float* x     = (const float*)d_in[0];
    const float* pos   = (const float*)d_in[1];
    const float* ln1_w = (const float*)d_in[2];
    const float* ln1_b = (const float*)d_in[3];
    const float* Wq    = (const float*)d_in[4];
    const float* bq    = (const float*)d_in[5];
    const float* Wk    = (const float*)d_in[6];
    const float* bk    = (const float*)d_in[7];
    const float* Wv    = (const float*)d_in[8];
    const float* bv    = (const float*)d_in[9];
    const float* Wo    = (const float*)d_in[10];
    const float* bo    = (const float*)d_in[11];
    const float* ln2_w = (const float*)d_in[12];
    const float* ln2_b = (const float*)d_in[13];
    const float* W1    = (const float*)d_in[14];
    const float* b1    = (const float*)d_in[15];
    const float* W2    = (const float*)d_in[16];
    const float* b2    = (const float*)d_in[17];
    float* out = (float*)d_out;

    void* p;
    cudaGetSymbolAddress(&p, g_h);    float* h    = (float*)p;
    cudaGetSymbolAddress(&p, g_q);    float* qb   = (float*)p;
    cudaGetSymbolAddress(&p, g_k);    float* kb   = (float*)p;
    cudaGetSymbolAddress(&p, g_v);    float* vb   = (float*)p;
    cudaGetSymbolAddress(&p, g_attn); float* ab   = (float*)p;
    cudaGetSymbolAddress(&p, g_x1);   float* x1   = (float*)p;
    cudaGetSymbolAddress(&p, g_hid);  float* hid  = (float*)p;
    cudaGetSymbolAddress(&p, g_knn);  int*   knn  = (int*)p;

    static bool attr_done = false;
    if (!attr_done) {
        cudaFuncSetAttribute(tc_gemm<0, 0>, cudaFuncAttributeMaxDynamicSharedMemorySize, SMEM_BYTES);
        cudaFuncSetAttribute(tc_gemm<0, 1>, cudaFuncAttributeMaxDynamicSharedMemorySize, SMEM_BYTES);
        cudaFuncSetAttribute(tc_gemm<1, 0>, cudaFuncAttributeMaxDynamicSharedMemorySize, SMEM_BYTES);
        attr_done = true;
    }

    // kNN graph: grid build + binned exact search
    zero_bins_kernel<<<(NBINS + 255) / 256, 256>>>();
    pack_count_kernel<<<N_PTS / 256, 256>>>(pos);
    scan_kernel<<<1, 1024>>>();
    scatter_kernel<<<N_PTS / 256, 256>>>();
    knn_bins_kernel<<<N_PTS / 8, 256>>>();

    // h = LN1(x)
    ln_kernel<<<N_PTS / 8, 256>>>(x, ln1_w, ln1_b, h);

    // fused q/k/v projections (z selects weight set)
    dim3 gqkv3(DIM / 128, N_PTS / 128, 3);
    tc_gemm<0, 0><<<gqkv3, 256, SMEM_BYTES>>>(h, Wq, Wk, Wv, bq, bk, bv,
                                              qb, kb, vb, nullptr, N_PTS, DIM, DIM);

    // local attention over kNN
    attn_kernel<<<N_PTS / 8, 256>>>(qb, kb, vb, knn, ab);

    // x1 = x + attn @ Wo^T + bo
    dim3 gqkv(DIM / 128, N_PTS / 128, 1);
    tc_gemm<0, 1><<<gqkv, 256, SMEM_BYTES>>>(ab, Wo, Wo, Wo, bo, bo, bo,
                                             x1, x1, x1, x, N_PTS, DIM, DIM);

    // h2 = LN2(x1)  (reuse h)
    ln_kernel<<<N_PTS / 8, 256>>>(x1, ln2_w, ln2_b, h);

    // hid = gelu(h2 @ W1^T + b1)
    dim3 gmlp1(MLP_HID / 128, N_PTS / 128, 1);
    tc_gemm<1, 0><<<gmlp1, 256, SMEM_BYTES>>>(h, W1, W1, W1, b1, b1, b1,
                                              hid, hid, hid, nullptr, N_PTS, MLP_HID, DIM);

    // out = x1 + hid @ W2^T + b2
    tc_gemm<0, 1><<<gqkv, 256, SMEM_BYTES>>>(hid, W2, W2, W2, b2, b2, b2,
                                             out, out, out, x1, N_PTS, DIM, MLP_HID);
}

// round 11
// speedup vs baseline: 1.6674x; 1.6674x over previous
#include <cuda_runtime.h>
#include <cuda_fp16.h>
#include <math.h>
#include <cstdint>

#define N_PTS 16384
#define DIM 256
#define HEADS 8
#define HD 32
#define KNN 20
#define MLP_HID 1024
#define SCALE 0.17677669529663687f  // 32^-0.5
#define FULLMASK 0xffffffffu

// spatial grid for kNN
#define NB 16
#define NBINS (NB * NB * NB)
#define XMIN (-4.25f)
#define CELL 0.53125f
#define INVCELL (1.0f / CELL)
#define DINF 3.0e38f
#define IINF 0x7fffffff

// ---------------- scratch (device globals; no allocation allowed) ----------
__device__ __half g_h16[N_PTS * DIM];       // LN out (1 then 2)
__device__ __half g_q16[N_PTS * DIM];
__device__ __half g_k16[N_PTS * DIM];
__device__ __half g_v16[N_PTS * DIM];
__device__ __half g_ab16[N_PTS * DIM];      // attention output
__device__ __half g_hid16[N_PTS * MLP_HID];
__device__ float  g_x1[N_PTS * DIM];        // residual-1 result (f32)
__device__ __half g_wq16[DIM * DIM];
__device__ __half g_wk16[DIM * DIM];
__device__ __half g_wv16[DIM * DIM];
__device__ __half g_wo16[DIM * DIM];
__device__ __half g_w116[MLP_HID * DIM];
__device__ __half g_w216[DIM * MLP_HID];
__device__ int    g_knn[N_PTS * KNN];
__device__ float4 g_pos4[N_PTS];
__device__ int    g_bincnt[NBINS];
__device__ int    g_binstart[NBINS + 1];
__device__ int    g_cursor[NBINS];
__device__ float4 g_spos[N_PTS];
__device__ int    g_sidx[N_PTS];

// ---------------- helpers ---------------------------------------------------
__device__ __forceinline__ void ld8h(const __half* p, float* f) {
    uint4 u = *(const uint4*)p;
    const __half2* hp = (const __half2*)&u;
#pragma unroll
    for (int i = 0; i < 4; i++) {
        float2 t = __half22float2(hp[i]);
        f[2 * i] = t.x; f[2 * i + 1] = t.y;
    }
}
__device__ __forceinline__ void st8h(__half* p, const float* f) {
    uint4 u;
    __half2* hp = (__half2*)&u;
#pragma unroll
    for (int i = 0; i < 4; i++) hp[i] = __floats2half2_rn(f[2 * i], f[2 * i + 1]);
    *(uint4*)p = u;
}

__device__ __forceinline__ void mma_f16(float* c, const uint32_t* a, const uint32_t* b) {
    asm volatile(
        "mma.sync.aligned.m16n8k16.row.col.f32.f16.f16.f32 "
        "{%0,%1,%2,%3}, {%4,%5,%6,%7}, {%8,%9}, {%0,%1,%2,%3};"
        : "+f"(c[0]), "+f"(c[1]), "+f"(c[2]), "+f"(c[3])
        : "r"(a[0]), "r"(a[1]), "r"(a[2]), "r"(a[3]), "r"(b[0]), "r"(b[1]));
}

__device__ __forceinline__ uint32_t s2u(const void* smem_ptr) {
    uint32_t addr;
    asm("{ .reg .u64 tmp; cvta.to.shared.u64 tmp, %1; cvt.u32.u64 %0, tmp; }"
        : "=r"(addr) : "l"(smem_ptr));
    return addr;
}
__device__ __forceinline__ void cp_async16(uint32_t smem_addr, const void* gptr) {
    asm volatile("cp.async.cg.shared.global [%0], [%1], 16;"
                 :: "r"(smem_addr), "l"(gptr));
}
__device__ __forceinline__ void cp_commit() {
    asm volatile("cp.async.commit_group;");
}
template <int NN>
__device__ __forceinline__ void cp_wait() {
    asm volatile("cp.async.wait_group %0;" :: "n"(NN));
}

// ==================== fp16 mma.sync GEMM (3-stage cp.async pipeline) =======
// C[M,Nn] = act(A[M,Kd] * B[Nn,Kd]^T + bias) [+ R]
// A,B fp16 in gmem. CTA tile 128x128, 8 warps (4m x 2n), warp tile 32x64,
// K chunk 64 halves (128B rows). XOR swizzle on 16B units: unit^(row&7) —
// conflict-free fragment loads. gridDim.z selects (B,bias,C) for QKV fusion.
#define ABUF 16384                 // bytes per stage per matrix (128 rows x 128B)
#define NSTAGE 3
#define SMEM_BYTES (2 * NSTAGE * ABUF)   // 96 KB

template <int ACT, int RES, int OUT16>
__global__ __launch_bounds__(256) void tc_gemm(const __half* __restrict__ A,
                                               const __half* __restrict__ B0,
                                               const __half* __restrict__ B1,
                                               const __half* __restrict__ B2,
                                               const float* __restrict__ bias0,
                                               const float* __restrict__ bias1,
                                               const float* __restrict__ bias2,
                                               void* C0v, void* C1v, void* C2v,
                                               const float* __restrict__ R,
                                               int M, int Nn, int Kd) {
    extern __shared__ char smem[];

    const __half* B    = (blockIdx.z == 0) ? B0    : (blockIdx.z == 1) ? B1    : B2;
    const float*  bias = (blockIdx.z == 0) ? bias0 : (blockIdx.z == 1) ? bias1 : bias2;
    void*         Cv   = (blockIdx.z == 0) ? C0v   : (blockIdx.z == 1) ? C1v   : C2v;

    const int tid = threadIdx.x;
    const int wid = tid >> 5;
    const int lane = tid & 31;
    const int g = lane >> 2;     // 0..7
    const int t = lane & 3;      // 0..3
    const int m0 = blockIdx.y * 128;
    const int n0 = blockIdx.x * 128;
    const int wm = (wid >> 1) * 32;
    const int wn = (wid & 1) * 64;

    float acc[2][8][4];
#pragma unroll
    for (int mt = 0; mt < 2; mt++)
#pragma unroll
        for (int nt = 0; nt < 8; nt++)
#pragma unroll
            for (int j = 0; j < 4; j++) acc[mt][nt][j] = 0.0f;

    // staging: thread handles row=tid>>1, half-row (4x 16B units)
    const int srow = tid >> 1;
    const int hsel = tid & 1;
    const __half* agbase = A + (size_t)(m0 + srow) * Kd + hsel * 32;
    const __half* bgbase = B + (size_t)(n0 + srow) * Kd + hsel * 32;
    const uint32_t smem_u = s2u(smem);
    const int nch = Kd >> 6;   // K chunk = 64 halves

    auto issue = [&](int ch) {
        const int buf = ch % NSTAGE;
        const __half* ag = agbase + ch * 64;
        const __half* bg = bgbase + ch * 64;
        const uint32_t rowoff = (uint32_t)srow * 128u;
        const uint32_t abuf = smem_u + buf * ABUF + rowoff;
        const uint32_t bbuf = smem_u + NSTAGE * ABUF + buf * ABUF + rowoff;
#pragma unroll
        for (int j = 0; j < 4; j++) {
            const uint32_t su = (uint32_t)((hsel * 4 + j) ^ (srow & 7)) << 4;
            cp_async16(abuf + su, ag + j * 8);
            cp_async16(bbuf + su, bg + j * 8);
        }
        cp_commit();
    };

    issue(0);
    if (nch > 1) issue(1);
    for (int ch = 0; ch < nch; ++ch) {
        if (ch + 1 < nch) cp_wait<1>();
        else              cp_wait<0>();
        __syncthreads();
        if (ch + 2 < nch) issue(ch + 2);

        const char* As = smem + (ch % NSTAGE) * ABUF;
        const char* Bs = smem + NSTAGE * ABUF + (ch % NSTAGE) * ABUF;
#pragma unroll
        for (int ks = 0; ks < 4; ks++) {
            const int su0 = ((2 * ks)     ^ g) * 16 + 4 * t;
            const int su1 = ((2 * ks + 1) ^ g) * 16 + 4 * t;
            uint32_t a[2][4];
#pragma unroll
            for (int mt = 0; mt < 2; mt++) {
                const char* p0 = As + (wm + mt * 16 + g) * 128;
                a[mt][0] = *(const uint32_t*)(p0 + su0);
                a[mt][1] = *(const uint32_t*)(p0 + 8 * 128 + su0);
                a[mt][2] = *(const uint32_t*)(p0 + su1);
                a[mt][3] = *(const uint32_t*)(p0 + 8 * 128 + su1);
            }
            uint32_t b[8][2];
#pragma unroll
            for (int nt = 0; nt < 8; nt++) {
                const char* pb = Bs + (wn + nt * 8 + g) * 128;
                b[nt][0] = *(const uint32_t*)(pb + su0);
                b[nt][1] = *(const uint32_t*)(pb + su1);
            }
#pragma unroll
            for (int mt = 0; mt < 2; mt++)
#pragma unroll
                for (int nt = 0; nt < 8; nt++)
                    mma_f16(acc[mt][nt], a[mt], b[nt]);
        }
    }

    // epilogue: D rows g/g+8 per mt, cols 2t,2t+1 per nt
#pragma unroll
    for (int mt = 0; mt < 2; mt++) {
#pragma unroll
        for (int half = 0; half < 2; half++) {
            const int m = m0 + wm + mt * 16 + g + half * 8;
            const float* rrow = R + (size_t)m * Nn + n0 + wn;
#pragma unroll
            for (int nt = 0; nt < 8; nt++) {
                const int nc = nt * 8 + 2 * t;
                float2 c;
                c.x = acc[mt][nt][half * 2 + 0] + bias[n0 + wn + nc + 0];
                c.y = acc[mt][nt][half * 2 + 1] + bias[n0 + wn + nc + 1];
                if (ACT == 1) {  // exact GELU
                    c.x = 0.5f * c.x * (1.0f + erff(c.x * 0.70710678118654752f));
                    c.y = 0.5f * c.y * (1.0f + erff(c.y * 0.70710678118654752f));
                }
                if (RES) {
                    c.x += rrow[nc + 0];
                    c.y += rrow[nc + 1];
                }
                if (OUT16) {
                    __half* crow = (__half*)Cv + (size_t)m * Nn + n0 + wn;
                    *(__half2*)(crow + nc) = __floats2half2_rn(c.x, c.y);
                } else {
                    float* crow = (float*)Cv + (size_t)m * Nn + n0 + wn;
                    *(float2*)(crow + nc) = c;
                }
            }
        }
    }
}

// ---------------- weight conversion f32 -> fp16 ----------------------------
__global__ __launch_bounds__(256) void cvt_w4_kernel(const float* __restrict__ s0,
                                                     const float* __restrict__ s1,
                                                     const float* __restrict__ s2,
                                                     const float* __restrict__ s3,
                                                     __half* d0, __half* d1,
                                                     __half* d2, __half* d3) {
    const float* src = (blockIdx.y == 0) ? s0 : (blockIdx.y == 1) ? s1
                      : (blockIdx.y == 2) ? s2 : s3;
    __half* dst = (blockIdx.y == 0) ? d0 : (blockIdx.y == 1) ? d1
                 : (blockIdx.y == 2) ? d2 : d3;
    const int i = (blockIdx.x * 256 + threadIdx.x) * 8;
    float f[8];
    *(float4*)(f)     = *(const float4*)(src + i);
    *(float4*)(f + 4) = *(const float4*)(src + i + 4);
    st8h(dst + i, f);
}

__global__ __launch_bounds__(256) void cvt_w2_kernel(const float* __restrict__ s0,
                                                     const float* __restrict__ s1,
                                                     __half* d0, __half* d1) {
    const float* src = (blockIdx.y == 0) ? s0 : s1;
    __half* dst = (blockIdx.y == 0) ? d0 : d1;
    const int i = (blockIdx.x * 256 + threadIdx.x) * 8;
    float f[8];
    *(float4*)(f)     = *(const float4*)(src + i);
    *(float4*)(f + 4) = *(const float4*)(src + i + 4);
    st8h(dst + i, f);
}

// ==================== grid-binned exact kNN ====================
__device__ __forceinline__ int bin_of(float x) {
    int b = (int)floorf((x - XMIN) * INVCELL);
    return min(NB - 1, max(0, b));
}

__global__ __launch_bounds__(256) void zero_bins_kernel() {
    const int i = blockIdx.x * blockDim.x + threadIdx.x;
    if (i < NBINS) g_bincnt[i] = 0;
}

__global__ __launch_bounds__(256) void pack_count_kernel(const float* __restrict__ pos) {
    const int i = blockIdx.x * blockDim.x + threadIdx.x;
    float4 p;
    p.x = pos[i * 3 + 0];
    p.y = pos[i * 3 + 1];
    p.z = pos[i * 3 + 2];
    p.w = 0.0f;
    g_pos4[i] = p;
    const int b = (bin_of(p.z) * NB + bin_of(p.y)) * NB + bin_of(p.x);
    atomicAdd(&g_bincnt[b], 1);
}

__global__ __launch_bounds__(1024) void scan_kernel() {
    __shared__ int ssum[1024];
    const int t = threadIdx.x;
    int c0 = g_bincnt[4 * t + 0];
    int c1 = g_bincnt[4 * t + 1];
    int c2 = g_bincnt[4 * t + 2];
    int c3 = g_bincnt[4 * t + 3];
    const int s = c0 + c1 + c2 + c3;
    ssum[t] = s;
    __syncthreads();
    for (int off = 1; off < 1024; off <<= 1) {
        int v = (t >= off) ? ssum[t - off] : 0;
        __syncthreads();
        ssum[t] += v;
        __syncthreads();
    }
    int excl = ssum[t] - s;
    g_binstart[4 * t + 0] = excl; g_cursor[4 * t + 0] = excl; excl += c0;
    g_binstart[4 * t + 1] = excl; g_cursor[4 * t + 1] = excl; excl += c1;
    g_binstart[4 * t + 2] = excl; g_cursor[4 * t + 2] = excl; excl += c2;
    g_binstart[4 * t + 3] = excl; g_cursor[4 * t + 3] = excl;
    if (t == 1023) g_binstart[NBINS] = N_PTS;
}

__global__ __launch_bounds__(256) void scatter_kernel() {
    const int i = blockIdx.x * blockDim.x + threadIdx.x;
    const float4 p = g_pos4[i];
    const int b = (bin_of(p.z) * NB + bin_of(p.y)) * NB + bin_of(p.x);
    const int pos = atomicAdd(&g_cursor[b], 1);
    g_spos[pos] = p;
    g_sidx[pos] = i;
}

// warp-per-query shell-expanding exact kNN (lexicographic (d, idx) top-21).
__global__ __launch_bounds__(256) void knn_bins_kernel() {
    const int lane = threadIdx.x & 31;
    const int warp = threadIdx.x >> 5;
    const int qi = blockIdx.x * 8 + warp;

    const float4 qp = g_pos4[qi];
    const float qx = qp.x, qy = qp.y, qz = qp.z;
    const int qbx = bin_of(qx), qby = bin_of(qy), qbz = bin_of(qz);

    float list_d = DINF;
    int   list_i = IINF;
    float tau = DINF;
    int   tau_i = IINF;

    for (int r = 0; r < NB; ++r) {
        if (r >= 2) {
            const float sm = (float)(r - 1) * CELL;
            if (sm * sm > tau * 1.001f) break;
        }
        for (int dz = -r; dz <= r; ++dz) {
            const int zz = qbz + dz;
            if (zz < 0 || zz >= NB) continue;
            for (int dy = -r; dy <= r; ++dy) {
                const int yy = qby + dy;
                if (yy < 0 || yy >= NB) continue;
                const bool face = (dz == r || dz == -r || dy == r || dy == -r);
                const int step = (face || r == 0) ? 1 : 2 * r;
                for (int dx = -r; dx <= r; dx += step) {
                    const int xx = qbx + dx;
                    if (xx < 0 || xx >= NB) continue;
                    const int bin = (zz * NB + yy) * NB + xx;
                    const int s0 = g_binstart[bin];
                    const int s1 = g_binstart[bin + 1];
                    if (s0 == s1) continue;

                    const float lox = (xx == 0)      ? -1e30f : XMIN + xx * CELL;
                    const float hix = (xx == NB - 1) ?  1e30f : XMIN + (xx + 1) * CELL;
                    const float loy = (yy == 0)      ? -1e30f : XMIN + yy * CELL;
                    const float hiy = (yy == NB - 1) ?  1e30f : XMIN + (yy + 1) * CELL;
                    const float loz = (zz == 0)      ? -1e30f : XMIN + zz * CELL;
                    const float hiz = (zz == NB - 1) ?  1e30f : XMIN + (zz + 1) * CELL;
                    const float ddx = fmaxf(0.0f, fmaxf(lox - qx, qx - hix));
                    const float ddy = fmaxf(0.0f, fmaxf(loy - qy, qy - hiy));
                    const float ddz = fmaxf(0.0f, fmaxf(loz - qz, qz - hiz));
                    const float mind2 = ddx * ddx + ddy * ddy + ddz * ddz;
                    if (mind2 > tau * 1.001f) continue;

                    for (int off = s0; off < s1; off += 32) {
                        const int j = off + lane;
                        float d = DINF;
                        int ci = IINF;
                        if (j < s1) {
                            const float4 c = g_spos[j];
                            const float ex = qx - c.x;
                            const float ey = qy - c.y;
                            const float ez = qz - c.z;
                            d = ex * ex + ey * ey + ez * ez;
                            ci = g_sidx[j];
                        }
                        const bool cand = (d < tau) || (d == tau && ci < tau_i);
                        unsigned m = __ballot_sync(FULLMASK, cand);
                        while (m) {
                            const int src = __ffs(m) - 1;
                            m &= m - 1;
                            const float d_new = __shfl_sync(FULLMASK, d, src);
                            const int   i_new = __shfl_sync(FULLMASK, ci, src);
                            if (d_new < tau || (d_new == tau && i_new < tau_i)) {
                                const unsigned less = __ballot_sync(FULLMASK,
                                    (list_d < d_new) || (list_d == d_new && list_i < i_new));
                                const int pos = __popc(less);
                                const float d_up = __shfl_up_sync(FULLMASK, list_d, 1);
                                const int   i_up = __shfl_up_sync(FULLMASK, list_i, 1);
                                if (lane > pos)       { list_d = d_up;  list_i = i_up;  }
                                else if (lane == pos) { list_d = d_new; list_i = i_new; }
                                if (lane > 20)        { list_d = DINF;  list_i = IINF;  }
                                tau   = __shfl_sync(FULLMASK, list_d, 20);
                                tau_i = __shfl_sync(FULLMASK, list_i, 20);
                            }
                        }
                    }
                }
            }
        }
    }
    if (lane >= 1 && lane <= 20)
        g_knn[qi * KNN + (lane - 1)] = list_i;
}

// ---------------- LayerNorm: one warp per row, fp16 output ------------------
__global__ __launch_bounds__(256) void ln_kernel(const float* __restrict__ x,
                                                 const float* __restrict__ w,
                                                 const float* __restrict__ b,
                                                 __half* __restrict__ out) {
    const int warp = threadIdx.x >> 5;
    const int lane = threadIdx.x & 31;
    const int n = blockIdx.x * 8 + warp;
    const float4* xr = (const float4*)(x + (size_t)n * DIM + lane * 8);
    float4 a0 = xr[0], a1 = xr[1];
    float s1 = a0.x + a0.y + a0.z + a0.w + a1.x + a1.y + a1.z + a1.w;
    float s2 = a0.x * a0.x + a0.y * a0.y + a0.z * a0.z + a0.w * a0.w +
               a1.x * a1.x + a1.y * a1.y + a1.z * a1.z + a1.w * a1.w;
#pragma unroll
    for (int off = 16; off > 0; off >>= 1) {
        s1 += __shfl_xor_sync(0xffffffffu, s1, off);
        s2 += __shfl_xor_sync(0xffffffffu, s2, off);
    }
    float m = s1 * (1.0f / DIM);
    float var = s2 * (1.0f / DIM) - m * m;
    float r = rsqrtf(var + 1e-5f);
    const float4* wr = (const float4*)(w + lane * 8);
    const float4* br = (const float4*)(b + lane * 8);
    float4 w0 = wr[0], w1 = wr[1], b0 = br[0], b1 = br[1];
    float f[8];
    f[0] = (a0.x - m) * r * w0.x + b0.x;
    f[1] = (a0.y - m) * r * w0.y + b0.y;
    f[2] = (a0.z - m) * r * w0.z + b0.z;
    f[3] = (a0.w - m) * r * w0.w + b0.w;
    f[4] = (a1.x - m) * r * w1.x + b1.x;
    f[5] = (a1.y - m) * r * w1.y + b1.y;
    f[6] = (a1.z - m) * r * w1.z + b1.z;
    f[7] = (a1.w - m) * r * w1.w + b1.w;
    st8h(out + (size_t)n * DIM + lane * 8, f);
}

// ---------------- local attention: one warp per point (fp16 I/O) -----------
__global__ __launch_bounds__(256) void attn_kernel(const __half* __restrict__ q,
                                                   const __half* __restrict__ k,
                                                   const __half* __restrict__ v,
                                                   const int* __restrict__ knn,
                                                   __half* __restrict__ out) {
    const int warp = threadIdx.x >> 5;
    const int lane = threadIdx.x & 31;
    const int n = blockIdx.x * 8 + warp;
    float qf[8];
    ld8h(q + (size_t)n * DIM + lane * 8, qf);

    int idx[KNN];
#pragma unroll
    for (int j = 0; j < KNN; j++) idx[j] = knn[n * KNN + j];

    float w[KNN];
#pragma unroll
    for (int j = 0; j < KNN; j++) {
        float kf[8];
        ld8h(k + (size_t)idx[j] * DIM + lane * 8, kf);
        float s = qf[0] * kf[0] + qf[1] * kf[1] + qf[2] * kf[2] + qf[3] * kf[3] +
                  qf[4] * kf[4] + qf[5] * kf[5] + qf[6] * kf[6] + qf[7] * kf[7];
        s += __shfl_xor_sync(0xffffffffu, s, 1);
        s += __shfl_xor_sync(0xffffffffu, s, 2);
        w[j] = s * SCALE;
    }
    float mx = -3.0e38f;
#pragma unroll
    for (int j = 0; j < KNN; j++) mx = fmaxf(mx, w[j]);
    float sum = 0.0f;
#pragma unroll
    for (int j = 0; j < KNN; j++) { w[j] = expf(w[j] - mx); sum += w[j]; }
    const float inv = 1.0f / sum;

    float o[8] = {0, 0, 0, 0, 0, 0, 0, 0};
#pragma unroll
    for (int j = 0; j < KNN; j++) {
        const float wj = w[j] * inv;
        float vf[8];
        ld8h(v + (size_t)idx[j] * DIM + lane * 8, vf);
#pragma unroll
        for (int e = 0; e < 8; e++) o[e] += wj * vf[e];
    }
    st8h(out + (size_t)n * DIM + lane * 8, o);
}

// ---------------- launch ---------------------------------------------------
extern "C" void kernel_launch(void* const* d_in, const int* in_sizes, int n_in,
                              void* d_out, int out_size) {
    const float* x     = (const float*)d_in[0];
    const float* pos   = (const float*)d_in[1];
    const float* ln1_w = (const float*)d_in[2];
    const float* ln1_b = (const float*)d_in[3];
    const float* Wq    = (const float*)d_in[4];
    const float* bq    = (const float*)d_in[5];
    const float* Wk    = (const float*)d_in[6];
    const float* bk    = (const float*)d_in[7];
    const float* Wv    = (const float*)d_in[8];
    const float* bv    = (const float*)d_in[9];
    const float* Wo    = (const float*)d_in[10];
    const float* bo    = (const float*)d_in[11];
    const float* ln2_w = (const float*)d_in[12];
    const float* ln2_b = (const float*)d_in[13];
    const float* W1    = (const float*)d_in[14];
    const float* b1    = (const float*)d_in[15];
    const float* W2    = (const float*)d_in[16];
    const float* b2    = (const float*)d_in[17];
    float* out = (float*)d_out;

    void* p;
    cudaGetSymbolAddress(&p, g_h16);   __half* h16  = (__half*)p;
    cudaGetSymbolAddress(&p, g_q16);   __half* q16  = (__half*)p;
    cudaGetSymbolAddress(&p, g_k16);   __half* k16  = (__half*)p;
    cudaGetSymbolAddress(&p, g_v16);   __half* v16  = (__half*)p;
    cudaGetSymbolAddress(&p, g_ab16);  __half* ab16 = (__half*)p;
    cudaGetSymbolAddress(&p, g_hid16); __half* hid16 = (__half*)p;
    cudaGetSymbolAddress(&p, g_x1);    float*  x1   = (float*)p;
    cudaGetSymbolAddress(&p, g_wq16);  __half* wq16 = (__half*)p;
    cudaGetSymbolAddress(&p, g_wk16);  __half* wk16 = (__half*)p;
    cudaGetSymbolAddress(&p, g_wv16);  __half* wv16 = (__half*)p;
    cudaGetSymbolAddress(&p, g_wo16);  __half* wo16 = (__half*)p;
    cudaGetSymbolAddress(&p, g_w116);  __half* w116 = (__half*)p;
    cudaGetSymbolAddress(&p, g_w216);  __half* w216 = (__half*)p;
    cudaGetSymbolAddress(&p, g_knn);   int*    knn  = (int*)p;

    static bool attr_done = false;
    if (!attr_done) {
        cudaFuncSetAttribute(tc_gemm<0, 0, 1>, cudaFuncAttributeMaxDynamicSharedMemorySize, SMEM_BYTES);
        cudaFuncSetAttribute(tc_gemm<0, 1, 0>, cudaFuncAttributeMaxDynamicSharedMemorySize, SMEM_BYTES);
        cudaFuncSetAttribute(tc_gemm<1, 0, 1>, cudaFuncAttributeMaxDynamicSharedMemorySize, SMEM_BYTES);
        attr_done = true;
    }

    // kNN graph: grid build + binned exact search
    zero_bins_kernel<<<(NBINS + 255) / 256, 256>>>();
    pack_count_kernel<<<N_PTS / 256, 256>>>(pos);
    scan_kernel<<<1, 1024>>>();
    scatter_kernel<<<N_PTS / 256, 256>>>();
    knn_bins_kernel<<<N_PTS / 8, 256>>>();

    // convert weights to fp16
    cvt_w4_kernel<<<dim3(DIM * DIM / 2048, 4), 256>>>(Wq, Wk, Wv, Wo,
                                                      wq16, wk16, wv16, wo16);
    cvt_w2_kernel<<<dim3(MLP_HID * DIM / 2048, 2), 256>>>(W1, W2, w116, w216);

    // h = LN1(x) -> fp16
    ln_kernel<<<N_PTS / 8, 256>>>(x, ln1_w, ln1_b, h16);

    // fused q/k/v projections (z selects weight set), fp16 out
    dim3 gqkv3(DIM / 128, N_PTS / 128, 3);
    tc_gemm<0, 0, 1><<<gqkv3, 256, SMEM_BYTES>>>(h16, wq16, wk16, wv16,
                                                 bq, bk, bv,
                                                 q16, k16, v16, nullptr,
                                                 N_PTS, DIM, DIM);

    // local attention over kNN (fp16 I/O)
    attn_kernel<<<N_PTS / 8, 256>>>(q16, k16, v16, knn, ab16);

    // x1 = x + attn @ Wo^T + bo (f32 out)
    dim3 gqkv(DIM / 128, N_PTS / 128, 1);
    tc_gemm<0, 1, 0><<<gqkv, 256, SMEM_BYTES>>>(ab16, wo16, wo16, wo16,
                                                bo, bo, bo,
                                                x1, x1, x1, x,
                                                N_PTS, DIM, DIM);

    // h2 = LN2(x1) -> fp16
    ln_kernel<<<N_PTS / 8, 256>>>(x1, ln2_w, ln2_b, h16);

    // hid = gelu(h2 @ W1^T + b1) -> fp16
    dim3 gmlp1(MLP_HID / 128, N_PTS / 128, 1);
    tc_gemm<1, 0, 1><<<gmlp1, 256, SMEM_BYTES>>>(h16, w116, w116, w116,
                                                 b1, b1, b1,
                                                 hid16, hid16, hid16, nullptr,
                                                 N_PTS, MLP_HID, DIM);

    // out = x1 + hid @ W2^T + b2 (f32 out)
    tc_gemm<0, 1, 0><<<gqkv, 256, SMEM_BYTES>>>(hid16, w216, w216, w216,
                                                b2, b2, b2,
                                                out, out, out, x1,
                                                N_PTS, DIM, MLP_HID);
}

// round 12
// speedup vs baseline: 1.8971x; 1.1377x over previous
#include <cuda_runtime.h>
#include <cuda_fp16.h>
#include <math.h>
#include <cstdint>

#define N_PTS 16384
#define DIM 256
#define HEADS 8
#define HD 32
#define KNN 20
#define MLP_HID 1024
#define SCALE 0.17677669529663687f  // 32^-0.5
#define FULLMASK 0xffffffffu

// spatial grid for kNN
#define NB 16
#define NBINS (NB * NB * NB)
#define XMIN (-4.25f)
#define CELL 0.53125f
#define INVCELL (1.0f / CELL)
#define DINF 3.0e38f
#define IINF 0x7fffffff

// ---------------- scratch (device globals; no allocation allowed) ----------
__device__ __half g_h16[N_PTS * DIM];       // LN out (1 then 2)
__device__ __half g_q16[N_PTS * DIM];
__device__ __half g_k16[N_PTS * DIM];
__device__ __half g_v16[N_PTS * DIM];
__device__ __half g_ab16[N_PTS * DIM];      // attention output
__device__ __half g_hid16[N_PTS * MLP_HID];
__device__ float  g_x1[N_PTS * DIM];        // residual-1 result (f32)
__device__ __half g_wq16[DIM * DIM];
__device__ __half g_wk16[DIM * DIM];
__device__ __half g_wv16[DIM * DIM];
__device__ __half g_wo16[DIM * DIM];
__device__ __half g_w116[MLP_HID * DIM];
__device__ __half g_w216[DIM * MLP_HID];
__device__ int    g_knn[N_PTS * KNN];
__device__ float4 g_pos4[N_PTS];
__device__ int    g_bincnt[NBINS];
__device__ int    g_binstart[NBINS + 1];
__device__ int    g_pr[N_PTS];              // packed (rank<<12)|bin per point
__device__ float4 g_spos[N_PTS];
__device__ int    g_sidx[N_PTS];

// ---------------- helpers ---------------------------------------------------
__device__ __forceinline__ void ld8h(const __half* p, float* f) {
    uint4 u = *(const uint4*)p;
    const __half2* hp = (const __half2*)&u;
#pragma unroll
    for (int i = 0; i < 4; i++) {
        float2 t = __half22float2(hp[i]);
        f[2 * i] = t.x; f[2 * i + 1] = t.y;
    }
}
__device__ __forceinline__ void st8h(__half* p, const float* f) {
    uint4 u;
    __half2* hp = (__half2*)&u;
#pragma unroll
    for (int i = 0; i < 4; i++) hp[i] = __floats2half2_rn(f[2 * i], f[2 * i + 1]);
    *(uint4*)p = u;
}

__device__ __forceinline__ void mma_f16(float* c, const uint32_t* a, const uint32_t* b) {
    asm volatile(
        "mma.sync.aligned.m16n8k16.row.col.f32.f16.f16.f32 "
        "{%0,%1,%2,%3}, {%4,%5,%6,%7}, {%8,%9}, {%0,%1,%2,%3};"
        : "+f"(c[0]), "+f"(c[1]), "+f"(c[2]), "+f"(c[3])
        : "r"(a[0]), "r"(a[1]), "r"(a[2]), "r"(a[3]), "r"(b[0]), "r"(b[1]));
}

__device__ __forceinline__ uint32_t s2u(const void* smem_ptr) {
    uint32_t addr;
    asm("{ .reg .u64 tmp; cvta.to.shared.u64 tmp, %1; cvt.u32.u64 %0, tmp; }"
        : "=r"(addr) : "l"(smem_ptr));
    return addr;
}
__device__ __forceinline__ void cp_async16(uint32_t smem_addr, const void* gptr) {
    asm volatile("cp.async.cg.shared.global [%0], [%1], 16;"
                 :: "r"(smem_addr), "l"(gptr));
}
__device__ __forceinline__ void cp_commit() {
    asm volatile("cp.async.commit_group;");
}
template <int NN>
__device__ __forceinline__ void cp_wait() {
    asm volatile("cp.async.wait_group %0;" :: "n"(NN));
}

// ==================== fp16 mma.sync GEMM (3-stage cp.async pipeline) =======
#define ABUF 16384                 // bytes per stage per matrix (128 rows x 128B)
#define NSTAGE 3
#define SMEM_BYTES (2 * NSTAGE * ABUF)   // 96 KB

template <int ACT, int RES, int OUT16>
__global__ __launch_bounds__(256) void tc_gemm(const __half* __restrict__ A,
                                               const __half* __restrict__ B0,
                                               const __half* __restrict__ B1,
                                               const __half* __restrict__ B2,
                                               const float* __restrict__ bias0,
                                               const float* __restrict__ bias1,
                                               const float* __restrict__ bias2,
                                               void* C0v, void* C1v, void* C2v,
                                               const float* __restrict__ R,
                                               int M, int Nn, int Kd) {
    extern __shared__ char smem[];

    const __half* B    = (blockIdx.z == 0) ? B0    : (blockIdx.z == 1) ? B1    : B2;
    const float*  bias = (blockIdx.z == 0) ? bias0 : (blockIdx.z == 1) ? bias1 : bias2;
    void*         Cv   = (blockIdx.z == 0) ? C0v   : (blockIdx.z == 1) ? C1v   : C2v;

    const int tid = threadIdx.x;
    const int wid = tid >> 5;
    const int lane = tid & 31;
    const int g = lane >> 2;
    const int t = lane & 3;
    const int m0 = blockIdx.y * 128;
    const int n0 = blockIdx.x * 128;
    const int wm = (wid >> 1) * 32;
    const int wn = (wid & 1) * 64;

    float acc[2][8][4];
#pragma unroll
    for (int mt = 0; mt < 2; mt++)
#pragma unroll
        for (int nt = 0; nt < 8; nt++)
#pragma unroll
            for (int j = 0; j < 4; j++) acc[mt][nt][j] = 0.0f;

    const int srow = tid >> 1;
    const int hsel = tid & 1;
    const __half* agbase = A + (size_t)(m0 + srow) * Kd + hsel * 32;
    const __half* bgbase = B + (size_t)(n0 + srow) * Kd + hsel * 32;
    const uint32_t smem_u = s2u(smem);
    const int nch = Kd >> 6;

    auto issue = [&](int ch) {
        const int buf = ch % NSTAGE;
        const __half* ag = agbase + ch * 64;
        const __half* bg = bgbase + ch * 64;
        const uint32_t rowoff = (uint32_t)srow * 128u;
        const uint32_t abuf = smem_u + buf * ABUF + rowoff;
        const uint32_t bbuf = smem_u + NSTAGE * ABUF + buf * ABUF + rowoff;
#pragma unroll
        for (int j = 0; j < 4; j++) {
            const uint32_t su = (uint32_t)((hsel * 4 + j) ^ (srow & 7)) << 4;
            cp_async16(abuf + su, ag + j * 8);
            cp_async16(bbuf + su, bg + j * 8);
        }
        cp_commit();
    };

    issue(0);
    if (nch > 1) issue(1);
    for (int ch = 0; ch < nch; ++ch) {
        if (ch + 1 < nch) cp_wait<1>();
        else              cp_wait<0>();
        __syncthreads();
        if (ch + 2 < nch) issue(ch + 2);

        const char* As = smem + (ch % NSTAGE) * ABUF;
        const char* Bs = smem + NSTAGE * ABUF + (ch % NSTAGE) * ABUF;
#pragma unroll
        for (int ks = 0; ks < 4; ks++) {
            const int su0 = ((2 * ks)     ^ g) * 16 + 4 * t;
            const int su1 = ((2 * ks + 1) ^ g) * 16 + 4 * t;
            uint32_t a[2][4];
#pragma unroll
            for (int mt = 0; mt < 2; mt++) {
                const char* p0 = As + (wm + mt * 16 + g) * 128;
                a[mt][0] = *(const uint32_t*)(p0 + su0);
                a[mt][1] = *(const uint32_t*)(p0 + 8 * 128 + su0);
                a[mt][2] = *(const uint32_t*)(p0 + su1);
                a[mt][3] = *(const uint32_t*)(p0 + 8 * 128 + su1);
            }
            uint32_t b[8][2];
#pragma unroll
            for (int nt = 0; nt < 8; nt++) {
                const char* pb = Bs + (wn + nt * 8 + g) * 128;
                b[nt][0] = *(const uint32_t*)(pb + su0);
                b[nt][1] = *(const uint32_t*)(pb + su1);
            }
#pragma unroll
            for (int mt = 0; mt < 2; mt++)
#pragma unroll
                for (int nt = 0; nt < 8; nt++)
                    mma_f16(acc[mt][nt], a[mt], b[nt]);
        }
    }

#pragma unroll
    for (int mt = 0; mt < 2; mt++) {
#pragma unroll
        for (int half = 0; half < 2; half++) {
            const int m = m0 + wm + mt * 16 + g + half * 8;
            const float* rrow = R + (size_t)m * Nn + n0 + wn;
#pragma unroll
            for (int nt = 0; nt < 8; nt++) {
                const int nc = nt * 8 + 2 * t;
                float2 c;
                c.x = acc[mt][nt][half * 2 + 0] + bias[n0 + wn + nc + 0];
                c.y = acc[mt][nt][half * 2 + 1] + bias[n0 + wn + nc + 1];
                if (ACT == 1) {
                    c.x = 0.5f * c.x * (1.0f + erff(c.x * 0.70710678118654752f));
                    c.y = 0.5f * c.y * (1.0f + erff(c.y * 0.70710678118654752f));
                }
                if (RES) {
                    c.x += rrow[nc + 0];
                    c.y += rrow[nc + 1];
                }
                if (OUT16) {
                    __half* crow = (__half*)Cv + (size_t)m * Nn + n0 + wn;
                    *(__half2*)(crow + nc) = __floats2half2_rn(c.x, c.y);
                } else {
                    float* crow = (float*)Cv + (size_t)m * Nn + n0 + wn;
                    *(float2*)(crow + nc) = c;
                }
            }
        }
    }
}

// ---------------- weight conversion f32 -> fp16 ----------------------------
__global__ __launch_bounds__(256) void cvt_w4_kernel(const float* __restrict__ s0,
                                                     const float* __restrict__ s1,
                                                     const float* __restrict__ s2,
                                                     const float* __restrict__ s3,
                                                     __half* d0, __half* d1,
                                                     __half* d2, __half* d3) {
    const float* src = (blockIdx.y == 0) ? s0 : (blockIdx.y == 1) ? s1
                      : (blockIdx.y == 2) ? s2 : s3;
    __half* dst = (blockIdx.y == 0) ? d0 : (blockIdx.y == 1) ? d1
                 : (blockIdx.y == 2) ? d2 : d3;
    const int i = (blockIdx.x * 256 + threadIdx.x) * 8;
    float f[8];
    *(float4*)(f)     = *(const float4*)(src + i);
    *(float4*)(f + 4) = *(const float4*)(src + i + 4);
    st8h(dst + i, f);
}

__global__ __launch_bounds__(256) void cvt_w2_kernel(const float* __restrict__ s0,
                                                     const float* __restrict__ s1,
                                                     __half* d0, __half* d1) {
    const float* src = (blockIdx.y == 0) ? s0 : s1;
    __half* dst = (blockIdx.y == 0) ? d0 : d1;
    const int i = (blockIdx.x * 256 + threadIdx.x) * 8;
    float f[8];
    *(float4*)(f)     = *(const float4*)(src + i);
    *(float4*)(f + 4) = *(const float4*)(src + i + 4);
    st8h(dst + i, f);
}

// ==================== grid-binned exact kNN ====================
__device__ __forceinline__ int bin_of(float x) {
    int b = (int)floorf((x - XMIN) * INVCELL);
    return min(NB - 1, max(0, b));
}

__global__ __launch_bounds__(256) void zero_bins_kernel() {
    const int i = blockIdx.x * blockDim.x + threadIdx.x;
    if (i < NBINS) g_bincnt[i] = 0;
}

// pack positions + histogram; atomic returns rank within bin (saved for scatter)
__global__ __launch_bounds__(256) void pack_count_kernel(const float* __restrict__ pos) {
    const int i = blockIdx.x * blockDim.x + threadIdx.x;
    float4 p;
    p.x = pos[i * 3 + 0];
    p.y = pos[i * 3 + 1];
    p.z = pos[i * 3 + 2];
    p.w = 0.0f;
    g_pos4[i] = p;
    const int b = (bin_of(p.z) * NB + bin_of(p.y)) * NB + bin_of(p.x);
    const int r = atomicAdd(&g_bincnt[b], 1);
    g_pr[i] = (r << 12) | b;
}

__global__ __launch_bounds__(1024) void scan_kernel() {
    __shared__ int ssum[1024];
    const int t = threadIdx.x;
    int c0 = g_bincnt[4 * t + 0];
    int c1 = g_bincnt[4 * t + 1];
    int c2 = g_bincnt[4 * t + 2];
    int c3 = g_bincnt[4 * t + 3];
    const int s = c0 + c1 + c2 + c3;
    ssum[t] = s;
    __syncthreads();
    for (int off = 1; off < 1024; off <<= 1) {
        int v = (t >= off) ? ssum[t - off] : 0;
        __syncthreads();
        ssum[t] += v;
        __syncthreads();
    }
    int excl = ssum[t] - s;
    g_binstart[4 * t + 0] = excl; excl += c0;
    g_binstart[4 * t + 1] = excl; excl += c1;
    g_binstart[4 * t + 2] = excl; excl += c2;
    g_binstart[4 * t + 3] = excl;
    if (t == 1023) g_binstart[NBINS] = N_PTS;
}

// atomic-free scatter using precomputed (rank, bin)
__global__ __launch_bounds__(256) void scatter_kernel() {
    const int i = blockIdx.x * blockDim.x + threadIdx.x;
    const int pr = g_pr[i];
    const int pos = g_binstart[pr & 4095] + (pr >> 12);
    g_spos[pos] = g_pos4[i];
    g_sidx[pos] = i;
}

// warp-per-query shell-expanding exact kNN (lexicographic (d, idx) top-21).
__global__ __launch_bounds__(256) void knn_bins_kernel() {
    const int lane = threadIdx.x & 31;
    const int warp = threadIdx.x >> 5;
    const int qi = blockIdx.x * 8 + warp;

    const float4 qp = g_pos4[qi];
    const float qx = qp.x, qy = qp.y, qz = qp.z;
    const int qbx = bin_of(qx), qby = bin_of(qy), qbz = bin_of(qz);

    float list_d = DINF;
    int   list_i = IINF;
    float tau = DINF;
    int   tau_i = IINF;

    for (int r = 0; r < NB; ++r) {
        if (r >= 2) {
            const float sm = (float)(r - 1) * CELL;
            if (sm * sm > tau * 1.001f) break;
        }
        for (int dz = -r; dz <= r; ++dz) {
            const int zz = qbz + dz;
            if (zz < 0 || zz >= NB) continue;
            for (int dy = -r; dy <= r; ++dy) {
                const int yy = qby + dy;
                if (yy < 0 || yy >= NB) continue;
                const bool face = (dz == r || dz == -r || dy == r || dy == -r);
                const int step = (face || r == 0) ? 1 : 2 * r;
                for (int dx = -r; dx <= r; dx += step) {
                    const int xx = qbx + dx;
                    if (xx < 0 || xx >= NB) continue;
                    const int bin = (zz * NB + yy) * NB + xx;
                    const int s0 = g_binstart[bin];
                    const int s1 = g_binstart[bin + 1];
                    if (s0 == s1) continue;

                    const float lox = (xx == 0)      ? -1e30f : XMIN + xx * CELL;
                    const float hix = (xx == NB - 1) ?  1e30f : XMIN + (xx + 1) * CELL;
                    const float loy = (yy == 0)      ? -1e30f : XMIN + yy * CELL;
                    const float hiy = (yy == NB - 1) ?  1e30f : XMIN + (yy + 1) * CELL;
                    const float loz = (zz == 0)      ? -1e30f : XMIN + zz * CELL;
                    const float hiz = (zz == NB - 1) ?  1e30f : XMIN + (zz + 1) * CELL;
                    const float ddx = fmaxf(0.0f, fmaxf(lox - qx, qx - hix));
                    const float ddy = fmaxf(0.0f, fmaxf(loy - qy, qy - hiy));
                    const float ddz = fmaxf(0.0f, fmaxf(loz - qz, qz - hiz));
                    const float mind2 = ddx * ddx + ddy * ddy + ddz * ddz;
                    if (mind2 > tau * 1.001f) continue;

                    for (int off = s0; off < s1; off += 32) {
                        const int j = off + lane;
                        float d = DINF;
                        int ci = IINF;
                        if (j < s1) {
                            const float4 c = g_spos[j];
                            const float ex = qx - c.x;
                            const float ey = qy - c.y;
                            const float ez = qz - c.z;
                            d = ex * ex + ey * ey + ez * ez;
                            ci = g_sidx[j];
                        }
                        const bool cand = (d < tau) || (d == tau && ci < tau_i);
                        unsigned m = __ballot_sync(FULLMASK, cand);
                        while (m) {
                            const int src = __ffs(m) - 1;
                            m &= m - 1;
                            const float d_new = __shfl_sync(FULLMASK, d, src);
                            const int   i_new = __shfl_sync(FULLMASK, ci, src);
                            if (d_new < tau || (d_new == tau && i_new < tau_i)) {
                                const unsigned less = __ballot_sync(FULLMASK,
                                    (list_d < d_new) || (list_d == d_new && list_i < i_new));
                                const int pos = __popc(less);
                                const float d_up = __shfl_up_sync(FULLMASK, list_d, 1);
                                const int   i_up = __shfl_up_sync(FULLMASK, list_i, 1);
                                if (lane > pos)       { list_d = d_up;  list_i = i_up;  }
                                else if (lane == pos) { list_d = d_new; list_i = i_new; }
                                if (lane > 20)        { list_d = DINF;  list_i = IINF;  }
                                tau   = __shfl_sync(FULLMASK, list_d, 20);
                                tau_i = __shfl_sync(FULLMASK, list_i, 20);
                            }
                        }
                    }
                }
            }
        }
    }
    if (lane >= 1 && lane <= 20)
        g_knn[qi * KNN + (lane - 1)] = list_i;
}

// ---------------- LayerNorm: one warp per row, fp16 output ------------------
__global__ __launch_bounds__(256) void ln_kernel(const float* __restrict__ x,
                                                 const float* __restrict__ w,
                                                 const float* __restrict__ b,
                                                 __half* __restrict__ out) {
    const int warp = threadIdx.x >> 5;
    const int lane = threadIdx.x & 31;
    const int n = blockIdx.x * 8 + warp;
    const float4* xr = (const float4*)(x + (size_t)n * DIM + lane * 8);
    float4 a0 = xr[0], a1 = xr[1];
    float s1 = a0.x + a0.y + a0.z + a0.w + a1.x + a1.y + a1.z + a1.w;
    float s2 = a0.x * a0.x + a0.y * a0.y + a0.z * a0.z + a0.w * a0.w +
               a1.x * a1.x + a1.y * a1.y + a1.z * a1.z + a1.w * a1.w;
#pragma unroll
    for (int off = 16; off > 0; off >>= 1) {
        s1 += __shfl_xor_sync(0xffffffffu, s1, off);
        s2 += __shfl_xor_sync(0xffffffffu, s2, off);
    }
    float m = s1 * (1.0f / DIM);
    float var = s2 * (1.0f / DIM) - m * m;
    float r = rsqrtf(var + 1e-5f);
    const float4* wr = (const float4*)(w + lane * 8);
    const float4* br = (const float4*)(b + lane * 8);
    float4 w0 = wr[0], w1 = wr[1], b0 = br[0], b1 = br[1];
    float f[8];
    f[0] = (a0.x - m) * r * w0.x + b0.x;
    f[1] = (a0.y - m) * r * w0.y + b0.y;
    f[2] = (a0.z - m) * r * w0.z + b0.z;
    f[3] = (a0.w - m) * r * w0.w + b0.w;
    f[4] = (a1.x - m) * r * w1.x + b1.x;
    f[5] = (a1.y - m) * r * w1.y + b1.y;
    f[6] = (a1.z - m) * r * w1.z + b1.z;
    f[7] = (a1.w - m) * r * w1.w + b1.w;
    st8h(out + (size_t)n * DIM + lane * 8, f);
}

// ---------------- local attention: one warp per point (fp16 I/O) -----------
__global__ __launch_bounds__(256) void attn_kernel(const __half* __restrict__ q,
                                                   const __half* __restrict__ k,
                                                   const __half* __restrict__ v,
                                                   const int* __restrict__ knn,
                                                   __half* __restrict__ out) {
    const int warp = threadIdx.x >> 5;
    const int lane = threadIdx.x & 31;
    const int n = blockIdx.x * 8 + warp;
    float qf[8];
    ld8h(q + (size_t)n * DIM + lane * 8, qf);

    int idx[KNN];
#pragma unroll
    for (int j = 0; j < KNN; j++) idx[j] = knn[n * KNN + j];

    float w[KNN];
#pragma unroll
    for (int j = 0; j < KNN; j++) {
        float kf[8];
        ld8h(k + (size_t)idx[j] * DIM + lane * 8, kf);
        float s = qf[0] * kf[0] + qf[1] * kf[1] + qf[2] * kf[2] + qf[3] * kf[3] +
                  qf[4] * kf[4] + qf[5] * kf[5] + qf[6] * kf[6] + qf[7] * kf[7];
        s += __shfl_xor_sync(0xffffffffu, s, 1);
        s += __shfl_xor_sync(0xffffffffu, s, 2);
        w[j] = s * SCALE;
    }
    float mx = -3.0e38f;
#pragma unroll
    for (int j = 0; j < KNN; j++) mx = fmaxf(mx, w[j]);
    float sum = 0.0f;
#pragma unroll
    for (int j = 0; j < KNN; j++) { w[j] = expf(w[j] - mx); sum += w[j]; }
    const float inv = 1.0f / sum;

    float o[8] = {0, 0, 0, 0, 0, 0, 0, 0};
#pragma unroll
    for (int j = 0; j < KNN; j++) {
        const float wj = w[j] * inv;
        float vf[8];
        ld8h(v + (size_t)idx[j] * DIM + lane * 8, vf);
#pragma unroll
        for (int e = 0; e < 8; e++) o[e] += wj * vf[e];
    }
    st8h(out + (size_t)n * DIM + lane * 8, o);
}

// ---------------- launch ---------------------------------------------------
extern "C" void kernel_launch(void* const* d_in, const int* in_sizes, int n_in,
                              void* d_out, int out_size) {
    const float* x     = (const float*)d_in[0];
    const float* pos   = (const float*)d_in[1];
    const float* ln1_w = (const float*)d_in[2];
    const float* ln1_b = (const float*)d_in[3];
    const float* Wq    = (const float*)d_in[4];
    const float* bq    = (const float*)d_in[5];
    const float* Wk    = (const float*)d_in[6];
    const float* bk    = (const float*)d_in[7];
    const float* Wv    = (const float*)d_in[8];
    const float* bv    = (const float*)d_in[9];
    const float* Wo    = (const float*)d_in[10];
    const float* bo    = (const float*)d_in[11];
    const float* ln2_w = (const float*)d_in[12];
    const float* ln2_b = (const float*)d_in[13];
    const float* W1    = (const float*)d_in[14];
    const float* b1    = (const float*)d_in[15];
    const float* W2    = (const float*)d_in[16];
    const float* b2    = (const float*)d_in[17];
    float* out = (float*)d_out;

    void* p;
    cudaGetSymbolAddress(&p, g_h16);   __half* h16  = (__half*)p;
    cudaGetSymbolAddress(&p, g_q16);   __half* q16  = (__half*)p;
    cudaGetSymbolAddress(&p, g_k16);   __half* k16  = (__half*)p;
    cudaGetSymbolAddress(&p, g_v16);   __half* v16  = (__half*)p;
    cudaGetSymbolAddress(&p, g_ab16);  __half* ab16 = (__half*)p;
    cudaGetSymbolAddress(&p, g_hid16); __half* hid16 = (__half*)p;
    cudaGetSymbolAddress(&p, g_x1);    float*  x1   = (float*)p;
    cudaGetSymbolAddress(&p, g_wq16);  __half* wq16 = (__half*)p;
    cudaGetSymbolAddress(&p, g_wk16);  __half* wk16 = (__half*)p;
    cudaGetSymbolAddress(&p, g_wv16);  __half* wv16 = (__half*)p;
    cudaGetSymbolAddress(&p, g_wo16);  __half* wo16 = (__half*)p;
    cudaGetSymbolAddress(&p, g_w116);  __half* w116 = (__half*)p;
    cudaGetSymbolAddress(&p, g_w216);  __half* w216 = (__half*)p;
    cudaGetSymbolAddress(&p, g_knn);   int*    knn  = (int*)p;

    static bool init_done = false;
    static cudaStream_t s_knn;
    static cudaEvent_t ev_root, ev_knn;
    if (!init_done) {
        cudaFuncSetAttribute(tc_gemm<0, 0, 1>, cudaFuncAttributeMaxDynamicSharedMemorySize, SMEM_BYTES);
        cudaFuncSetAttribute(tc_gemm<0, 1, 0>, cudaFuncAttributeMaxDynamicSharedMemorySize, SMEM_BYTES);
        cudaFuncSetAttribute(tc_gemm<1, 0, 1>, cudaFuncAttributeMaxDynamicSharedMemorySize, SMEM_BYTES);
        cudaStreamCreateWithFlags(&s_knn, cudaStreamNonBlocking);
        cudaEventCreateWithFlags(&ev_root, cudaEventDisableTiming);
        cudaEventCreateWithFlags(&ev_knn, cudaEventDisableTiming);
        init_done = true;
    }

    // ---- fork: kNN chain on side stream, feature path on stream 0 ----
    cudaEventRecord(ev_root, 0);
    cudaStreamWaitEvent(s_knn, ev_root, 0);

    zero_bins_kernel<<<(NBINS + 255) / 256, 256, 0, s_knn>>>();
    pack_count_kernel<<<N_PTS / 256, 256, 0, s_knn>>>(pos);
    scan_kernel<<<1, 1024, 0, s_knn>>>();
    scatter_kernel<<<N_PTS / 256, 256, 0, s_knn>>>();
    knn_bins_kernel<<<N_PTS / 8, 256, 0, s_knn>>>();
    cudaEventRecord(ev_knn, s_knn);

    // feature path (stream 0): weight cvt, LN1, QKV
    cvt_w4_kernel<<<dim3(DIM * DIM / 2048, 4), 256>>>(Wq, Wk, Wv, Wo,
                                                      wq16, wk16, wv16, wo16);
    cvt_w2_kernel<<<dim3(MLP_HID * DIM / 2048, 2), 256>>>(W1, W2, w116, w216);
    ln_kernel<<<N_PTS / 8, 256>>>(x, ln1_w, ln1_b, h16);

    dim3 gqkv3(DIM / 128, N_PTS / 128, 3);
    tc_gemm<0, 0, 1><<<gqkv3, 256, SMEM_BYTES>>>(h16, wq16, wk16, wv16,
                                                 bq, bk, bv,
                                                 q16, k16, v16, nullptr,
                                                 N_PTS, DIM, DIM);

    // ---- join: attn needs both qkv and knn ----
    cudaStreamWaitEvent(0, ev_knn, 0);
    attn_kernel<<<N_PTS / 8, 256>>>(q16, k16, v16, knn, ab16);

    // x1 = x + attn @ Wo^T + bo (f32 out)
    dim3 gqkv(DIM / 128, N_PTS / 128, 1);
    tc_gemm<0, 1, 0><<<gqkv, 256, SMEM_BYTES>>>(ab16, wo16, wo16, wo16,
                                                bo, bo, bo,
                                                x1, x1, x1, x,
                                                N_PTS, DIM, DIM);

    // h2 = LN2(x1) -> fp16
    ln_kernel<<<N_PTS / 8, 256>>>(x1, ln2_w, ln2_b, h16);

    // hid = gelu(h2 @ W1^T + b1) -> fp16
    dim3 gmlp1(MLP_HID / 128, N_PTS / 128, 1);
    tc_gemm<1, 0, 1><<<gmlp1, 256, SMEM_BYTES>>>(h16, w116, w116, w116,
                                                 b1, b1, b1,
                                                 hid16, hid16, hid16, nullptr,
                                                 N_PTS, MLP_HID, DIM);

    // out = x1 + hid @ W2^T + b2 (f32 out)
    tc_gemm<0, 1, 0><<<gqkv, 256, SMEM_BYTES>>>(hid16, w216, w216, w216,
                                                b2, b2, b2,
                                                out, out, out, x1,
                                                N_PTS, DIM, MLP_HID);
}